// round 17
// baseline (speedup 1.0000x reference)
#include <cuda_runtime.h>

// Problem dims (fixed by the dataset)
#define BDIM 64
#define NDIM 512
#define HDIM 2048
#define KP     (NDIM / 2)     // 256 packed k-pairs
#define HC     64             // h-chunk per prod block
#define NCHUNK (HDIM / HC)    // 32 partial-product chunks
#define NSPLIT 8              // n-split for z-GEMM
#define NCK    (NDIM / NSPLIT)

// ---------------------------------------------------------------------------
// Device scratch (allocation-free rule: __device__ globals)
// ---------------------------------------------------------------------------
__device__ float              g_Tt[HDIM * BDIM];                  // [h][b] = tanh(z[b][h])
__device__ unsigned long long g_zp[NSPLIT * HDIM * (BDIM / 2)];   // z partials [ns][h][bp] packed
__device__ unsigned long long g_Ppart[NCHUNK * BDIM * KP];        // [c][b][kp] partial ratio-products

// ---------------------------------------------------------------------------
// f32x2 packed helpers
// ---------------------------------------------------------------------------
__device__ __forceinline__ unsigned long long pk2(float lo, float hi) {
    unsigned long long r;
    asm("mov.b64 %0, {%1, %2};" : "=l"(r) : "f"(lo), "f"(hi));
    return r;
}
__device__ __forceinline__ unsigned long long pk2u(unsigned int lo, unsigned int hi) {
    unsigned long long r;
    asm("mov.b64 %0, {%1, %2};" : "=l"(r) : "r"(lo), "r"(hi));
    return r;
}
__device__ __forceinline__ unsigned long long fma2(unsigned long long a, unsigned long long b, unsigned long long c) {
    unsigned long long r;
    asm("fma.rn.f32x2 %0, %1, %2, %3;" : "=l"(r) : "l"(a), "l"(b), "l"(c));
    return r;
}
__device__ __forceinline__ unsigned long long mul2(unsigned long long a, unsigned long long b) {
    unsigned long long r;
    asm("mul.rn.f32x2 %0, %1, %2;" : "=l"(r) : "l"(a), "l"(b));
    return r;
}
__device__ __forceinline__ unsigned long long add2(unsigned long long a, unsigned long long b) {
    unsigned long long r;
    asm("add.rn.f32x2 %0, %1, %2;" : "=l"(r) : "l"(a), "l"(b));
    return r;
}
__device__ __forceinline__ float2 up2(unsigned long long p) {
    float lo, hi;
    asm("mov.b64 {%0, %1}, %2;" : "=f"(lo), "=f"(hi) : "l"(p));
    return make_float2(lo, hi);
}
__device__ __forceinline__ float tanh_fast(float v) {
    float r;
    asm("tanh.approx.f32 %0, %1;" : "=f"(r) : "f"(v));
    return r;
}

// ---------------------------------------------------------------------------
// Kernel 1: z partials. Thread = (1 h, 16 b as 8 packed accs), n-chunk NCK=64.
// grid (HDIM/256, BDIM/16, NSPLIT) = (8, 4, 8) = 256 blocks, block 256.
// ---------------------------------------------------------------------------
__global__ void __launch_bounds__(256) z_part_kernel(const float* __restrict__ W,
                                                     const float* __restrict__ x) {
    __shared__ float sx[NCK][16];  // [n_local][b_local]
    int t  = threadIdx.x;
    int h  = blockIdx.x * 256 + t;
    int b0 = blockIdx.y * 16;
    int n0 = blockIdx.z * NCK;

#pragma unroll
    for (int j = 0; j < 4; j++) {
        int idx = t + j * 256;               // 0..1023
        int bl = idx >> 6, nl = idx & 63;
        sx[nl][bl] = __ldg(x + (size_t)(b0 + bl) * NDIM + n0 + nl);
    }
    __syncthreads();

    unsigned long long acc[8];
#pragma unroll
    for (int i = 0; i < 8; i++) acc[i] = 0;  // packed +0.0

    const float* wp = W + (size_t)n0 * HDIM + h;
#pragma unroll 4
    for (int n = 0; n < NCK; n++) {
        float w = __ldg(wp + n * HDIM);      // coalesced across threads
        unsigned long long wd = pk2(w, w);
        const ulonglong2* xr = reinterpret_cast<const ulonglong2*>(&sx[n][0]);
        ulonglong2 xA = xr[0];               // b0+0..3  (broadcast)
        ulonglong2 xB = xr[1];               // b0+4..7
        ulonglong2 xC = xr[2];               // b0+8..11
        ulonglong2 xD = xr[3];               // b0+12..15
        acc[0] = fma2(xA.x, wd, acc[0]);
        acc[1] = fma2(xA.y, wd, acc[1]);
        acc[2] = fma2(xB.x, wd, acc[2]);
        acc[3] = fma2(xB.y, wd, acc[3]);
        acc[4] = fma2(xC.x, wd, acc[4]);
        acc[5] = fma2(xC.y, wd, acc[5]);
        acc[6] = fma2(xD.x, wd, acc[6]);
        acc[7] = fma2(xD.y, wd, acc[7]);
    }
    int bp0 = blockIdx.y * 8;
    ulonglong2* zp = reinterpret_cast<ulonglong2*>(
        g_zp + ((size_t)blockIdx.z * HDIM + h) * (BDIM / 2) + bp0);
#pragma unroll
    for (int i = 0; i < 4; i++)
        zp[i] = make_ulonglong2(acc[2 * i], acc[2 * i + 1]);
}

// ---------------------------------------------------------------------------
// Kernel 2: combine z partials + bias, tanh.approx, write Tt[h][b].
// grid 256, block 256 (thread = (h, bp)); 8 independent loads (MLP 8).
// ---------------------------------------------------------------------------
__global__ void __launch_bounds__(256) z_comb_kernel(const float* __restrict__ bias) {
    int idx = blockIdx.x * 256 + threadIdx.x;   // 0..65535
    int h = idx >> 5, bp = idx & 31;
    const unsigned long long* zp = g_zp + (size_t)h * (BDIM / 2) + bp;
    unsigned long long v[NSPLIT];
#pragma unroll
    for (int ns = 0; ns < NSPLIT; ns++)
        v[ns] = __ldg(zp + (size_t)ns * (HDIM * BDIM / 2));
    unsigned long long s = add2(add2(add2(v[0], v[1]), add2(v[2], v[3])),
                                add2(add2(v[4], v[5]), add2(v[6], v[7])));
    float2 z = up2(s);
    float bv = bias[h];
    float2 tv = make_float2(tanh_fast(z.x + bv), tanh_fast(z.y + bv));
    *reinterpret_cast<float2*>(g_Tt + (size_t)h * BDIM + 2 * bp) = tv;
}

// ---------------------------------------------------------------------------
// Kernel 3: main product kernel with fused C/S generation.
//   Ppart[c][b][k] = prod_{h in chunk} ( cosh(2W[k,h]) - x[b,k]*tanh(z[b,h])*sinh(2W[k,h]) )
// x = +-1 exactly, so -x*t is a SIGN-BIT XOR (alu pipe), not a multiply:
// inner step per acc = 2 LOP3 + fma2 + mul2 -> fma-pipe ops drop 24->16 per h.
// Thread tile: 1 kp (2 k) x 8 b over 64 h. grid (KP/32, 1, NCHUNK) = 256
// blocks, block 256, 2 blocks/SM -> single wave on 148 SMs.
// ---------------------------------------------------------------------------
__global__ void __launch_bounds__(256, 2) prod_kernel(const float* __restrict__ W,
                                                      const float* __restrict__ x) {
    __shared__ float sC[HC][66];   // pad 66: conflict-free, LDS.64-aligned
    __shared__ float sS[HC][66];
    int t    = threadIdx.x;
    int lane = t & 31;
    int w    = t >> 5;
    int k0   = blockIdx.x * 64;    // 64 k = 32 kp per block
    int h0   = blockIdx.z * HC;

    // Build C/S tile: coalesced W reads (lanes cover consecutive h), MUFU expf
#pragma unroll
    for (int j = 0; j < 16; j++) {
        int idx = t + j * 256;                // 0..4095 over 64k x 64h
        int hl = idx & 63, kl = idx >> 6;
        float wv = __ldg(W + (size_t)(k0 + kl) * HDIM + h0 + hl);
        float e  = __expf(2.0f * wv);
        float ei = __expf(-2.0f * wv);
        sC[hl][kl] = 0.5f * (e + ei);
        sS[hl][kl] = 0.5f * (e - ei);
    }

    // Sign masks for 8 b at this thread's kp: flip bit set where x > 0,
    // so t ^ msk == -x * t exactly (x is +-1).
    int b0 = w * 8;
    unsigned int mlo[8], mhi[8];
#pragma unroll
    for (int i = 0; i < 8; i++) {
        unsigned long long xv = *reinterpret_cast<const unsigned long long*>(
            x + (size_t)(b0 + i) * NDIM + k0 + 2 * lane);
        unsigned long long m = (~xv) & 0x8000000080000000ULL;
        mlo[i] = (unsigned int)m;
        mhi[i] = (unsigned int)(m >> 32);
    }
    __syncthreads();

    const float4* tp = reinterpret_cast<const float4*>(g_Tt + (size_t)h0 * BDIM + b0);

    unsigned long long acc[8];
#pragma unroll
    for (int i = 0; i < 8; i++) acc[i] = pk2(1.0f, 1.0f);

#pragma unroll 4
    for (int h = 0; h < HC; h++) {
        unsigned long long Cp = *reinterpret_cast<const unsigned long long*>(&sC[h][2 * lane]);
        unsigned long long Sp = *reinterpret_cast<const unsigned long long*>(&sS[h][2 * lane]);
        float4 ta = __ldg(tp + h * (BDIM / 4));       // tanh b0..b0+3 (uniform)
        float4 tb = __ldg(tp + h * (BDIM / 4) + 1);   // tanh b0+4..b0+7
        unsigned int u0 = __float_as_uint(ta.x);
        unsigned int u1 = __float_as_uint(ta.y);
        unsigned int u2 = __float_as_uint(ta.z);
        unsigned int u3 = __float_as_uint(ta.w);
        unsigned int u4 = __float_as_uint(tb.x);
        unsigned int u5 = __float_as_uint(tb.y);
        unsigned int u6 = __float_as_uint(tb.z);
        unsigned int u7 = __float_as_uint(tb.w);
        acc[0] = mul2(acc[0], fma2(pk2u(u0 ^ mlo[0], u0 ^ mhi[0]), Sp, Cp));
        acc[1] = mul2(acc[1], fma2(pk2u(u1 ^ mlo[1], u1 ^ mhi[1]), Sp, Cp));
        acc[2] = mul2(acc[2], fma2(pk2u(u2 ^ mlo[2], u2 ^ mhi[2]), Sp, Cp));
        acc[3] = mul2(acc[3], fma2(pk2u(u3 ^ mlo[3], u3 ^ mhi[3]), Sp, Cp));
        acc[4] = mul2(acc[4], fma2(pk2u(u4 ^ mlo[4], u4 ^ mhi[4]), Sp, Cp));
        acc[5] = mul2(acc[5], fma2(pk2u(u5 ^ mlo[5], u5 ^ mhi[5]), Sp, Cp));
        acc[6] = mul2(acc[6], fma2(pk2u(u6 ^ mlo[6], u6 ^ mhi[6]), Sp, Cp));
        acc[7] = mul2(acc[7], fma2(pk2u(u7 ^ mlo[7], u7 ^ mhi[7]), Sp, Cp));
    }

    int kp = blockIdx.x * 32 + lane;
    unsigned long long* out = g_Ppart + (size_t)blockIdx.z * (BDIM * KP);
#pragma unroll
    for (int i = 0; i < 8; i++)
        out[(size_t)(b0 + i) * KP + kp] = acc[i];
}

// ---------------------------------------------------------------------------
// Kernel 4: fused reduce, chunk-product parallelized across threads.
// grid BDIM, block 1024: thread = (kp, cg), cg in 0..3, each multiplies 8
// independent chunk values (MLP-8); partials combined via smem; first 256
// threads apply ea = Oxy*exp(-2*x*a) and tree-sum over k.
// ---------------------------------------------------------------------------
__global__ void __launch_bounds__(1024) reduce_kernel(const float* __restrict__ x,
                                                      const float* __restrict__ a,
                                                      const float* __restrict__ Oxy,
                                                      float* __restrict__ out) {
    __shared__ unsigned long long sp[1024];
    __shared__ float ssum[8];
    int b  = blockIdx.x;
    int t  = threadIdx.x;
    int kp = t & 255;
    int cg = t >> 8;            // 0..3 -> chunks cg*8 .. cg*8+7

    const unsigned long long* P =
        g_Ppart + (size_t)(cg * 8) * (BDIM * KP) + (size_t)b * KP + kp;
    unsigned long long v[8];
#pragma unroll
    for (int i = 0; i < 8; i++)
        v[i] = __ldg(P + (size_t)i * (BDIM * KP));
    sp[t] = mul2(mul2(mul2(v[0], v[1]), mul2(v[2], v[3])),
                 mul2(mul2(v[4], v[5]), mul2(v[6], v[7])));
    __syncthreads();

    if (t < 256) {
        unsigned long long p = mul2(mul2(sp[t], sp[t + 256]),
                                    mul2(sp[t + 512], sp[t + 768]));
        float2 pf = up2(p);
        float2 xv = *reinterpret_cast<const float2*>(x + (size_t)b * NDIM + 2 * kp);
        float2 av = *reinterpret_cast<const float2*>(a + 2 * kp);
        float2 ov = *reinterpret_cast<const float2*>(Oxy + 2 * kp);
        float e0 = ov.x * __expf(-2.0f * xv.x * av.x);
        float e1 = ov.y * __expf(-2.0f * xv.y * av.y);
        float s = pf.x * e0 + pf.y * e1;

#pragma unroll
        for (int o = 16; o; o >>= 1) s += __shfl_xor_sync(0xffffffffu, s, o);
        if ((t & 31) == 0) ssum[t >> 5] = s;
    }
    __syncthreads();
    if (t < 8) {
        float s2 = ssum[t];
#pragma unroll
        for (int o = 4; o; o >>= 1) s2 += __shfl_xor_sync(0x000000ffu, s2, o);
        if (t == 0) out[b] = s2;
    }
}

// ---------------------------------------------------------------------------
// Launch: 4 kernels
// ---------------------------------------------------------------------------
extern "C" void kernel_launch(void* const* d_in, const int* in_sizes, int n_in,
                              void* d_out, int out_size) {
    const float* x    = (const float*)d_in[0];   // [64,512]
    const float* W    = (const float*)d_in[1];   // [512,2048]
    const float* bias = (const float*)d_in[2];   // [2048]
    const float* a    = (const float*)d_in[3];   // [512]
    const float* Oxy  = (const float*)d_in[4];   // [512]
    float* out = (float*)d_out;                  // [64]

    z_part_kernel<<<dim3(HDIM / 256, BDIM / 16, NSPLIT), 256>>>(W, x);
    z_comb_kernel<<<256, 256>>>(bias);
    prod_kernel<<<dim3(KP / 32, 1, NCHUNK), 256>>>(W, x);
    reduce_kernel<<<BDIM, 1024>>>(x, a, Oxy, out);
}